// round 2
// baseline (speedup 1.0000x reference)
#include <cuda_runtime.h>
#include <cuda_bf16.h>

// DiceLoss fused kernel for GB300 (sm_103a).
// predict: [N=16, C=4, H=768, W=768] f32
// target:  [N, H, W] i32 in [0, C)
// masks:   [N, H, W] i32 in {0, 1}
// out:     scalar f32
//
// Per-pixel (derived from reference):
//   sm = softmax over C of predict; t = target; mk = (mask >= 1)
//   num[t] += mk ? sm[t] : 1
//   den[c] += mk ? sm[c]^2 : 0   (all c)
//   den[t] += mk ? 1 : 2
// final = sum_{n,c} (1 - (num[n,c]+1)/(den[n,c]+1)) / (N*C)

#define NB   16          // batch
#define NC   4           // classes
#define MPX  (768*768)   // pixels per image (589824)
#define MV   (MPX/4)     // float4 units per plane (147456)
#define BPI  72          // blocks per image
#define TPB  256         // threads per block
// per-thread trip count: MV / (BPI*TPB) = 8 exactly

__device__ float g_partials[NB * BPI * 8];

__device__ __forceinline__ void pixel(
    float x0, float x1, float x2, float x3, int tt, int mm,
    float& num0, float& num1, float& num2, float& num3,
    float& den0, float& den1, float& den2, float& den3)
{
    // softmax over 4 classes
    float mx = fmaxf(fmaxf(x0, x1), fmaxf(x2, x3));
    float e0 = __expf(x0 - mx);
    float e1 = __expf(x1 - mx);
    float e2 = __expf(x2 - mx);
    float e3 = __expf(x3 - mx);
    float inv = __frcp_rn(e0 + e1 + e2 + e3);
    float s0 = e0 * inv, s1 = e1 * inv, s2 = e2 * inv, s3 = e3 * inv;

    float fm = (mm >= 1) ? 1.0f : 0.0f;   // mask as float

    // den += mask * sm^2  (branchless FFMA)
    den0 = fmaf(fm, s0 * s0, den0);
    den1 = fmaf(fm, s1 * s1, den1);
    den2 = fmaf(fm, s2 * s2, den2);
    den3 = fmaf(fm, s3 * s3, den3);

    // one-hot contributions at class tt (branchless selects)
    float st   = (tt == 0) ? s0 : (tt == 1) ? s1 : (tt == 2) ? s2 : s3;
    float nadd = fm * st + (1.0f - fm);   // mk ? sm[t] : 1
    float dadd = 2.0f - fm;               // mk ? 1 : 2
    float h0 = (tt == 0) ? 1.0f : 0.0f;
    float h1 = (tt == 1) ? 1.0f : 0.0f;
    float h2 = (tt == 2) ? 1.0f : 0.0f;
    float h3 = (tt == 3) ? 1.0f : 0.0f;
    num0 = fmaf(h0, nadd, num0);  den0 = fmaf(h0, dadd, den0);
    num1 = fmaf(h1, nadd, num1);  den1 = fmaf(h1, dadd, den1);
    num2 = fmaf(h2, nadd, num2);  den2 = fmaf(h2, dadd, den2);
    num3 = fmaf(h3, nadd, num3);  den3 = fmaf(h3, dadd, den3);
}

__global__ __launch_bounds__(TPB)
void dice_pass1(const float* __restrict__ predict,
                const int*   __restrict__ target,
                const int*   __restrict__ masks)
{
    const int n   = blockIdx.y;
    const int bx  = blockIdx.x;
    const int tid = threadIdx.x;

    const float4* p0 = reinterpret_cast<const float4*>(predict + (size_t)n * NC * MPX);
    const float4* p1 = p0 + MV;
    const float4* p2 = p0 + 2 * MV;
    const float4* p3 = p0 + 3 * MV;
    const int4*   tg = reinterpret_cast<const int4*>(target + (size_t)n * MPX);
    const int4*   mk = reinterpret_cast<const int4*>(masks  + (size_t)n * MPX);

    float num0 = 0.f, num1 = 0.f, num2 = 0.f, num3 = 0.f;
    float den0 = 0.f, den1 = 0.f, den2 = 0.f, den3 = 0.f;

    const int stride = BPI * TPB;
    int v = bx * TPB + tid;
    // exact trip count 8; unroll x2 so 12 independent LDG.128 are in flight
    #pragma unroll 2
    for (int it = 0; it < 8; it++, v += stride) {
        float4 a = p0[v];
        float4 b = p1[v];
        float4 c = p2[v];
        float4 d = p3[v];
        int4   t = tg[v];
        int4   m = mk[v];

        pixel(a.x, b.x, c.x, d.x, t.x, m.x, num0, num1, num2, num3, den0, den1, den2, den3);
        pixel(a.y, b.y, c.y, d.y, t.y, m.y, num0, num1, num2, num3, den0, den1, den2, den3);
        pixel(a.z, b.z, c.z, d.z, t.z, m.z, num0, num1, num2, num3, den0, den1, den2, den3);
        pixel(a.w, b.w, c.w, d.w, t.w, m.w, num0, num1, num2, num3, den0, den1, den2, den3);
    }

    // deterministic block-level tree reduction of 8 values
    __shared__ float sh[8][TPB];
    sh[0][tid] = num0; sh[1][tid] = num1; sh[2][tid] = num2; sh[3][tid] = num3;
    sh[4][tid] = den0; sh[5][tid] = den1; sh[6][tid] = den2; sh[7][tid] = den3;
    __syncthreads();
    #pragma unroll
    for (int off = TPB / 2; off > 0; off >>= 1) {
        if (tid < off) {
            #pragma unroll
            for (int k = 0; k < 8; k++) sh[k][tid] += sh[k][tid + off];
        }
        __syncthreads();
    }
    if (tid < 8) {
        g_partials[((size_t)n * BPI + bx) * 8 + tid] = sh[tid][0];
    }
}

__global__ void dice_pass2(float* __restrict__ out)
{
    const int tid = threadIdx.x;  // 64 threads: one per (n, c)
    __shared__ float sh[64];
    float loss = 0.f;
    if (tid < NB * NC) {
        int n = tid / NC;
        int c = tid % NC;
        float num = 0.f, den = 0.f;
        #pragma unroll 8
        for (int b = 0; b < BPI; b++) {
            num += g_partials[((size_t)n * BPI + b) * 8 + c];
            den += g_partials[((size_t)n * BPI + b) * 8 + 4 + c];
        }
        loss = 1.0f - (num + 1.0f) / (den + 1.0f);
    }
    sh[tid] = loss;
    __syncthreads();
    #pragma unroll
    for (int off = 32; off > 0; off >>= 1) {
        if (tid < off) sh[tid] += sh[tid + off];
        __syncthreads();
    }
    if (tid == 0) out[0] = sh[0] / (float)(NB * NC);
}

extern "C" void kernel_launch(void* const* d_in, const int* in_sizes, int n_in,
                              void* d_out, int out_size)
{
    const float* predict = (const float*)d_in[0];
    const int*   target  = (const int*)d_in[1];
    const int*   masks   = (const int*)d_in[2];
    float* out = (float*)d_out;

    dim3 grid(BPI, NB);
    dice_pass1<<<grid, TPB>>>(predict, target, masks);
    dice_pass2<<<1, 64>>>(out);
}

// round 3
// speedup vs baseline: 1.0892x; 1.0892x over previous
#include <cuda_runtime.h>
#include <cuda_bf16.h>

// DiceLoss fused single-kernel for GB300 (sm_103a).
// predict: [N=16, C=4, H=768, W=768] f32
// target:  [N, H, W] i32 in [0, C)
// masks:   [N, H, W] i32 in {0, 1}
// out:     scalar f32
//
// Per-pixel (derived from reference):
//   sm = softmax over C of predict; t = target; mk = (mask >= 1)
//   num[t] += mk ? sm[t] : 1
//   den[c] += mk ? sm[c]^2 : 0   (all c)
//   den[t] += mk ? 1 : 2
// final = sum_{n,c} (1 - (num[n,c]+1)/(den[n,c]+1)) / (N*C)
//
// Finalization is fused via the threadfence-reduction "last block" pattern:
// no second kernel launch (the R2 profile showed the tiny pass2 kernel cost
// 9.8us of the 49.6us total).

#define NB   16          // batch
#define NC   4           // classes
#define MPX  (768*768)   // pixels per image (589824)
#define MV   (MPX/4)     // float4 units per plane (147456)
#define BPI  72          // blocks per image
#define TPB  256         // threads per block
#define TOT_BLOCKS (NB * BPI)   // 1152
// per-thread trip count: MV / (BPI*TPB) = 8 exactly

__device__ float g_partials[TOT_BLOCKS * 8];
__device__ unsigned int g_count = 0;   // ticket counter; last block resets it

__device__ __forceinline__ void pixel(
    float x0, float x1, float x2, float x3, int tt, int mm,
    float& num0, float& num1, float& num2, float& num3,
    float& den0, float& den1, float& den2, float& den3)
{
    // softmax over 4 classes
    float mx = fmaxf(fmaxf(x0, x1), fmaxf(x2, x3));
    float e0 = __expf(x0 - mx);
    float e1 = __expf(x1 - mx);
    float e2 = __expf(x2 - mx);
    float e3 = __expf(x3 - mx);
    float inv = __frcp_rn(e0 + e1 + e2 + e3);
    float s0 = e0 * inv, s1 = e1 * inv, s2 = e2 * inv, s3 = e3 * inv;

    float fm = (mm >= 1) ? 1.0f : 0.0f;   // mask as float

    // den += mask * sm^2 (branchless FFMA)
    den0 = fmaf(fm, s0 * s0, den0);
    den1 = fmaf(fm, s1 * s1, den1);
    den2 = fmaf(fm, s2 * s2, den2);
    den3 = fmaf(fm, s3 * s3, den3);

    // one-hot contributions at class tt (branchless selects)
    float st   = (tt == 0) ? s0 : (tt == 1) ? s1 : (tt == 2) ? s2 : s3;
    float nadd = fm * st + (1.0f - fm);   // mk ? sm[t] : 1
    float dadd = 2.0f - fm;               // mk ? 1 : 2
    float h0 = (tt == 0) ? 1.0f : 0.0f;
    float h1 = (tt == 1) ? 1.0f : 0.0f;
    float h2 = (tt == 2) ? 1.0f : 0.0f;
    float h3 = (tt == 3) ? 1.0f : 0.0f;
    num0 = fmaf(h0, nadd, num0);  den0 = fmaf(h0, dadd, den0);
    num1 = fmaf(h1, nadd, num1);  den1 = fmaf(h1, dadd, den1);
    num2 = fmaf(h2, nadd, num2);  den2 = fmaf(h2, dadd, den2);
    num3 = fmaf(h3, nadd, num3);  den3 = fmaf(h3, dadd, den3);
}

__global__ __launch_bounds__(TPB)
void dice_fused(const float* __restrict__ predict,
                const int*   __restrict__ target,
                const int*   __restrict__ masks,
                float*       __restrict__ out)
{
    const int n   = blockIdx.y;
    const int bx  = blockIdx.x;
    const int tid = threadIdx.x;
    const int lane = tid & 31;
    const int wid  = tid >> 5;

    const float4* p0 = reinterpret_cast<const float4*>(predict + (size_t)n * NC * MPX);
    const float4* p1 = p0 + MV;
    const float4* p2 = p0 + 2 * MV;
    const float4* p3 = p0 + 3 * MV;
    const int4*   tg = reinterpret_cast<const int4*>(target + (size_t)n * MPX);
    const int4*   mk = reinterpret_cast<const int4*>(masks  + (size_t)n * MPX);

    float acc[8];
    #pragma unroll
    for (int k = 0; k < 8; k++) acc[k] = 0.f;

    const int stride = BPI * TPB;
    int v = bx * TPB + tid;
    // exact trip count 8; unroll x2 so 12 independent LDG.128 in flight
    #pragma unroll 2
    for (int it = 0; it < 8; it++, v += stride) {
        float4 a = p0[v];
        float4 b = p1[v];
        float4 c = p2[v];
        float4 d = p3[v];
        int4   t = tg[v];
        int4   m = mk[v];

        pixel(a.x, b.x, c.x, d.x, t.x, m.x, acc[0], acc[1], acc[2], acc[3], acc[4], acc[5], acc[6], acc[7]);
        pixel(a.y, b.y, c.y, d.y, t.y, m.y, acc[0], acc[1], acc[2], acc[3], acc[4], acc[5], acc[6], acc[7]);
        pixel(a.z, b.z, c.z, d.z, t.z, m.z, acc[0], acc[1], acc[2], acc[3], acc[4], acc[5], acc[6], acc[7]);
        pixel(a.w, b.w, c.w, d.w, t.w, m.w, acc[0], acc[1], acc[2], acc[3], acc[4], acc[5], acc[6], acc[7]);
    }

    // warp-level shuffle reduction of 8 accumulators (deterministic)
    #pragma unroll
    for (int off = 16; off > 0; off >>= 1) {
        #pragma unroll
        for (int k = 0; k < 8; k++)
            acc[k] += __shfl_down_sync(0xffffffffu, acc[k], off);
    }

    __shared__ float swarp[8][8];   // [warp][value]
    if (lane == 0) {
        #pragma unroll
        for (int k = 0; k < 8; k++) swarp[wid][k] = acc[k];
    }
    __syncthreads();

    // threads 0..7: final cross-warp sum of value k = tid, publish partials
    if (tid < 8) {
        float s = 0.f;
        #pragma unroll
        for (int w = 0; w < 8; w++) s += swarp[w][tid];
        g_partials[((size_t)n * BPI + bx) * 8 + tid] = s;
        __threadfence();            // make partials visible device-wide
    }
    __syncthreads();

    // ticket: last block to arrive does the finalization
    __shared__ bool isLast;
    if (tid == 0) {
        unsigned int old = atomicAdd(&g_count, 1u);
        isLast = (old == TOT_BLOCKS - 1u);
    }
    __syncthreads();
    if (!isLast) return;

    // ---- finalization tail (single block, ~36KB from L2) ----
    // pair = (n,c) index 0..63; 4 threads per pair, each sums 18 blocks.
    const int pair = tid >> 2;       // 0..63
    const int sub  = tid & 3;
    const int nn   = pair >> 2;      // 0..15
    const int cc   = pair & 3;       // 0..3

    float num = 0.f, den = 0.f;
    #pragma unroll 6
    for (int b = sub; b < BPI; b += 4) {
        const float* base = &g_partials[((size_t)nn * BPI + b) * 8];
        num += __ldcg(base + cc);
        den += __ldcg(base + 4 + cc);
    }
    // combine the 4 sub-sums (lanes pair*4+sub are contiguous in a warp)
    num += __shfl_xor_sync(0xffffffffu, num, 1);
    num += __shfl_xor_sync(0xffffffffu, num, 2);
    den += __shfl_xor_sync(0xffffffffu, den, 1);
    den += __shfl_xor_sync(0xffffffffu, den, 2);

    float contrib = (sub == 0) ? (1.0f - (num + 1.0f) / (den + 1.0f)) : 0.f;

    // warp reduce, then cross-warp via smem
    #pragma unroll
    for (int off = 16; off > 0; off >>= 1)
        contrib += __shfl_down_sync(0xffffffffu, contrib, off);

    __shared__ float sfin[8];
    if (lane == 0) sfin[wid] = contrib;
    __syncthreads();
    if (tid == 0) {
        float s = 0.f;
        #pragma unroll
        for (int w = 0; w < 8; w++) s += sfin[w];
        out[0] = s / (float)(NB * NC);
        g_count = 0;   // reset for next graph replay (deterministic)
    }
}

extern "C" void kernel_launch(void* const* d_in, const int* in_sizes, int n_in,
                              void* d_out, int out_size)
{
    const float* predict = (const float*)d_in[0];
    const int*   target  = (const int*)d_in[1];
    const int*   masks   = (const int*)d_in[2];
    float* out = (float*)d_out;

    dim3 grid(BPI, NB);
    dice_fused<<<grid, TPB>>>(predict, target, masks, out);
}